// round 13
// baseline (speedup 1.0000x reference)
#include <cuda_runtime.h>
#include <cuda_bf16.h>
#include <math.h>
#include <stdint.h>

#define BB 64
#define NN 128
#define LL 64
#define DD 768
#define NEGV (-9e9f)
#define NCH 12            // K chunks of 64
#define NUNITS 2048       // 64 i x 32 jg

// -------- device scratch (no cudaMalloc allowed) ---------------------------
__device__ __nv_bfloat16 g_tAh[BB * NN * DD];
__device__ __nv_bfloat16 g_tAl[BB * NN * DD];
__device__ __nv_bfloat16 g_tBh[BB * LL * DD];
__device__ __nv_bfloat16 g_tBl[BB * LL * DD];
__device__ float g_S[BB * BB];
__device__ float g_P[BB * LL * NN];
__device__ int g_cA[BB];
__device__ int g_cB[BB];
__device__ int g_mapA[BB][NN];
__device__ int g_mapB[BB][LL];
__device__ int g_qhead;

// -------- helpers ----------------------------------------------------------
__device__ __forceinline__ uint32_t smem_u32(const void* p) {
    uint32_t a;
    asm("{ .reg .u64 t; cvta.to.shared.u64 t, %1; cvt.u32.u64 %0, t; }" : "=r"(a) : "l"(p));
    return a;
}
__device__ __forceinline__ void cp16(uint32_t dst, const void* src) {
    unsigned long long g = (unsigned long long)__cvta_generic_to_global(src);
    asm volatile("cp.async.cg.shared.global [%0], [%1], 16;" :: "r"(dst), "l"(g));
}
#define CP_COMMIT() asm volatile("cp.async.commit_group;" ::: "memory")

#define LDSM_X4(r0, r1, r2, r3, a) \
    asm volatile("ldmatrix.sync.aligned.m8n8.x4.shared.b16 {%0,%1,%2,%3}, [%4];" \
                 : "=r"(r0), "=r"(r1), "=r"(r2), "=r"(r3) : "r"(a))
#define LDSM_X2(r0, r1, a) \
    asm volatile("ldmatrix.sync.aligned.m8n8.x2.shared.b16 {%0,%1}, [%2];" \
                 : "=r"(r0), "=r"(r1) : "r"(a))

#define MMA_BF16(d, a, b) \
    asm("mma.sync.aligned.m16n8k16.row.col.f32.bf16.bf16.f32 " \
        "{%0,%1,%2,%3},{%4,%5,%6,%7},{%8,%9},{%0,%1,%2,%3};" \
        : "+f"((d)[0]), "+f"((d)[1]), "+f"((d)[2]), "+f"((d)[3]) \
        : "r"((a)[0]), "r"((a)[1]), "r"((a)[2]), "r"((a)[3]), \
          "r"((b)[0]), "r"((b)[1]))

// FMA-pipe exp (no MUFU): exp(x), x<=0, poly exp2 deg-6
__device__ __forceinline__ float fexp(float x) {
    float t = fmaxf(x * 1.44269504089f, -126.f);
    int   ni = __float2int_rn(t);
    float f  = t - (float)ni;
    float p = 1.54653240e-4f;
    p = fmaf(p, f, 1.33335581e-3f);
    p = fmaf(p, f, 9.61812910e-3f);
    p = fmaf(p, f, 5.55041087e-2f);
    p = fmaf(p, f, 2.40226507e-1f);
    p = fmaf(p, f, 6.93147182e-1f);
    p = fmaf(p, f, 1.0f);
    return __int_as_float(__float_as_int(p) + (ni << 23));
}

// f32x2 helpers (i2s kernel)
__device__ __forceinline__ void ffma2(unsigned long long &c, unsigned long long a,
                                      unsigned long long b) {
    asm("fma.rn.f32x2 %0, %1, %2, %0;" : "+l"(c) : "l"(a), "l"(b));
}
__device__ __forceinline__ unsigned long long pack2(float x, float y) {
    unsigned long long r;
    asm("mov.b64 %0, {%1, %2};" : "=l"(r) : "f"(x), "f"(y));
    return r;
}
__device__ __forceinline__ float2 unpack2(unsigned long long v) {
    float2 f;
    asm("mov.b64 {%0, %1}, %2;" : "=f"(f.x), "=f"(f.y) : "l"(v));
    return f;
}

// ---------------------------------------------------------------------------
// Kernel 0: mask-compacting f32 -> bf16 hi/lo split into pre-swizzled chunks.
// Also resets the persistent work queue each launch/replay.
// ---------------------------------------------------------------------------
__global__ void conv2(const float* __restrict__ text, const float* __restrict__ img,
                      const int* __restrict__ tmask, const int* __restrict__ imask)
{
    __shared__ int fA[NN], fB[LL];
    __shared__ int pfxA[NN + 1], pfxB[LL + 1];
    const int b  = blockIdx.x;
    const int dp = blockIdx.y;       // 0..3
    const int t  = threadIdx.x;      // 256

    if (b == 0 && dp == 0 && t == 0) g_qhead = 0;   // queue reset (pre-ground5)

    if (t < NN) fA[t] = (tmask[b * NN + t] != 0);
    if (t < LL) fB[t] = (imask[b * LL + t] != 0);
    __syncthreads();
    if (t == 0) {
        int s = 0;
        for (int n = 0; n < NN; n++) { pfxA[n] = s; s += fA[n]; }
        pfxA[NN] = s;
        s = 0;
        for (int l = 0; l < LL; l++) { pfxB[l] = s; s += fB[l]; }
        pfxB[LL] = s;
    }
    __syncthreads();
    const int cA = pfxA[NN], cB = pfxB[LL];
    const int cApad = (cA + 15) & ~15;
    const int cBpad = (cB + 7) & ~7;

    if (dp == 0) {
        if (t == 0) { g_cA[b] = cA; g_cB[b] = cB; }
        if (t < NN && fA[t]) g_mapA[b][pfxA[t]] = t;
        if (t < LL && fB[t]) g_mapB[b][pfxB[t]] = t;
    }

    const int d0 = dp * 192;
    for (int idx = t; idx < NN * 192; idx += 256) {
        int n = idx / 192, d = d0 + idx % 192;
        if (fA[n]) {
            float v = text[(size_t)b * NN * DD + n * DD + d];
            __nv_bfloat16 hi = __float2bfloat16(v);
            __nv_bfloat16 lo = __float2bfloat16(v - __bfloat162float(hi));
            int r = pfxA[n];
            int c = d >> 6, kin = d & 63;
            int off = ((b * NCH + c) * NN + r) * 64 + (kin ^ ((r & 7) << 3));
            g_tAh[off] = hi; g_tAl[off] = lo;
        }
    }
    for (int idx = t; idx < (cApad - cA) * 192; idx += 256) {
        int r = cA + idx / 192, d = d0 + idx % 192;
        int c = d >> 6, kin = d & 63;
        int off = ((b * NCH + c) * NN + r) * 64 + (kin ^ ((r & 7) << 3));
        g_tAh[off] = __float2bfloat16(0.f); g_tAl[off] = __float2bfloat16(0.f);
    }
    for (int idx = t; idx < LL * 192; idx += 256) {
        int l = idx / 192, d = d0 + idx % 192;
        if (fB[l]) {
            float v = img[(size_t)b * LL * DD + l * DD + d];
            __nv_bfloat16 hi = __float2bfloat16(v);
            __nv_bfloat16 lo = __float2bfloat16(v - __bfloat162float(hi));
            int r = pfxB[l];
            int c = d >> 6, kin = d & 63;
            int off = ((b * NCH + c) * LL + r) * 64 + (kin ^ ((r & 7) << 3));
            g_tBh[off] = hi; g_tBl[off] = lo;
        }
    }
    for (int idx = t; idx < (cBpad - cB) * 192; idx += 256) {
        int r = cB + idx / 192, d = d0 + idx % 192;
        int c = d >> 6, kin = d & 63;
        int off = ((b * NCH + c) * LL + r) * 64 + (kin ^ ((r & 7) << 3));
        g_tBh[off] = __float2bfloat16(0.f); g_tBl[off] = __float2bfloat16(0.f);
    }
}

// ---------------------------------------------------------------------------
// Stage one K-chunk (64 k) of COMPACTED data, bounds-guarded.
// ---------------------------------------------------------------------------
__device__ __forceinline__ void issue_chunk(uint32_t B0, int i, int jg, int c, int t,
                                            int limA, int cB0p, int cB1p)
{
    const __nv_bfloat16* Ah = g_tAh + (size_t)(i * NCH + c) * (NN * 64);
    const __nv_bfloat16* Al = g_tAl + (size_t)(i * NCH + c) * (NN * 64);
#pragma unroll
    for (int q = 0; q < 4; q++) {
        int idx = t + q * 256;
        if (idx < limA) {
            cp16(B0 + idx * 16, Ah + idx * 8);
            cp16(B0 + 16384 + idx * 16, Al + idx * 8);
        }
    }
#pragma unroll
    for (int q = 0; q < 4; q++) {
        int idx = t + q * 256;
        int row = idx >> 3;
        int jj = row >> 6;
        int srow = row & 63;
        bool ok = jj ? (srow < cB1p) : (srow < cB0p);
        if (ok) {
            size_t so = (size_t)((jg * 2 + jj) * NCH + c) * (LL * 64) + (size_t)(srow * 8 + (idx & 7)) * 8;
            cp16(B0 + 32768 + idx * 16, g_tBh + so);
            cp16(B0 + 49152 + idx * 16, g_tBl + so);
        }
    }
}

// ---------------------------------------------------------------------------
// Kernel A: PERSISTENT compacted bf16 3x GEMM + fused softmax epilogue.
// grid = 148 CTAs; units (i,jg) pulled from a global atomic queue.
// ---------------------------------------------------------------------------
__global__ __launch_bounds__(256, 1)
void ground6(const int* __restrict__ tmask)
{
    extern __shared__ __align__(16) char dsm[];   // 131072: 2x64KB stage / att
    __shared__ int   tm_s[NN];
    __shared__ int   mapA_s[NN];
    __shared__ int   mapB_s[NN];
    __shared__ float row_s1[NN];
    __shared__ float col_s2[LL];
    __shared__ int   u_s;

    const int t   = threadIdx.x;
    const int wid = t >> 5, lane = t & 31;
    const uint32_t sb = smem_u32(dsm);

    // lane constants (unit-independent)
    const int lr = lane & 15, half = lane >> 4;
    const int xorA = (lr & 7) << 4;
    const int blB = lane & 7;
    const int kBo = ((lane >> 3) & 1) << 4;
    const int xorB2 = blB << 4;
    const int mh = wid >> 2, ng = wid & 3;
    const int gr = lane >> 2, cp2 = (lane & 3) * 2;

    while (true) {
        if (t == 0) u_s = atomicAdd(&g_qhead, 1);
        __syncthreads();
        const int u = u_s;
        if (u >= NUNITS) break;
        const int i  = u >> 5;
        const int jg = u & 31;

        const int cA  = g_cA[i];
        const int cApad = (cA + 15) & ~15;
        const int cB0 = g_cB[jg * 2];
        const int cB1 = g_cB[jg * 2 + 1];
        const int cB0p = (cB0 + 7) & ~7;
        const int cB1p = (cB1 + 7) & ~7;

        if (t < NN) {
            tm_s[t]   = tmask[i * NN + t];
            mapA_s[t] = g_mapA[i][t];
            mapB_s[t] = g_mapB[jg * 2 + (t >> 6)][t & 63];
        }

        // ---- balanced warp tile assignment (warp-uniform) ------------------
        const int TM = cApad >> 4;
        int mrow[4]; int tmA = 0;
#pragma unroll
        for (int mf = 0; mf < 4; mf++) {
            int r = mh + 2 * mf;
            if (r < TM) mrow[tmA++] = r << 4;
        }
        const int T0 = cB0p >> 3, T1 = cB1p >> 3, TT = T0 + T1;
        int ncol[4]; int ntq = 0;
#pragma unroll
        for (int q = 0; q < 4; q++) {
            int p = ng + 4 * q;
            if (p < TT) ncol[ntq++] = (p < T0) ? (p << 3) : (64 + ((p - T0) << 3));
        }

        float acc[4][4][4];
#pragma unroll
        for (int a = 0; a < 4; a++)
#pragma unroll
            for (int b = 0; b < 4; b++)
#pragma unroll
                for (int r = 0; r < 4; r++) acc[a][b][r] = 0.f;

        const int limA = cApad * 8;

        issue_chunk(sb, i, jg, 0, t, limA, cB0p, cB1p);
        CP_COMMIT();

        for (int c = 0; c < NCH; c++) {
            const uint32_t SB = sb + (c & 1) * 65536;
            if (c + 1 < NCH) {
                issue_chunk(sb + ((c + 1) & 1) * 65536, i, jg, c + 1, t, limA, cB0p, cB1p);
                CP_COMMIT();
                asm volatile("cp.async.wait_group 1;" ::: "memory");
            } else {
                asm volatile("cp.async.wait_group 0;" ::: "memory");
            }
            __syncthreads();

            const uint32_t Ah = SB, Al = SB + 16384, Bh = SB + 32768, Bl = SB + 49152;
#pragma unroll
            for (int s = 0; s < 4; s++) {
                const int kb = s * 32;
                const int kaA = (kb | (half << 4)) ^ xorA;
                const int kaB = (kb | kBo) ^ xorB2;

                uint32_t ah[4][4], al[4][4], bh[4][2], bl2[4][2];
#pragma unroll
                for (int v = 0; v < 4; v++) if (v < tmA) {
                    int row = mrow[v] + lr;
                    LDSM_X4(ah[v][0], ah[v][1], ah[v][2], ah[v][3], Ah + row * 128 + kaA);
                    LDSM_X4(al[v][0], al[v][1], al[v][2], al[v][3], Al + row * 128 + kaA);
                }
#pragma unroll
                for (int q = 0; q < 4; q++) if (q < ntq) {
                    uint32_t off = (uint32_t)(ncol[q] + blB) * 128 + kaB;
                    LDSM_X2(bh[q][0],  bh[q][1],  Bh + off);
                    LDSM_X2(bl2[q][0], bl2[q][1], Bl + off);
                }
#pragma unroll
                for (int v = 0; v < 4; v++) if (v < tmA)
#pragma unroll
                    for (int q = 0; q < 4; q++) if (q < ntq)
                        MMA_BF16(acc[v][q], ah[v], bh[q]);
#pragma unroll
                for (int v = 0; v < 4; v++) if (v < tmA)
#pragma unroll
                    for (int q = 0; q < 4; q++) if (q < ntq)
                        MMA_BF16(acc[v][q], ah[v], bl2[q]);
#pragma unroll
                for (int v = 0; v < 4; v++) if (v < tmA)
#pragma unroll
                    for (int q = 0; q < 4; q++) if (q < ntq)
                        MMA_BF16(acc[v][q], al[v], bh[q]);
            }
            __syncthreads();
        }

        // ---- att tile -> SMEM (compacted coords), pitch 132 ---------------
        float* att = (float*)dsm;
#pragma unroll
        for (int v = 0; v < 4; v++) if (v < tmA)
#pragma unroll
            for (int q = 0; q < 4; q++) if (q < ntq) {
                int row = mrow[v] + gr;
                int col = ncol[q] + cp2;
                float* d = acc[v][q];
                float2 v0, v1;
                v0.x = (d[0] != 0.f) ? d[0] : NEGV;
                v0.y = (d[1] != 0.f) ? d[1] : NEGV;
                v1.x = (d[2] != 0.f) ? d[2] : NEGV;
                v1.y = (d[3] != 0.f) ? d[3] : NEGV;
                *(float2*)&att[row * 132 + col]       = v0;
                *(float2*)&att[(row + 8) * 132 + col] = v1;
            }
        __syncthreads();

        // ---- epilogue per image batch -------------------------------------
        for (int jj = 0; jj < 2; jj++) {
            const int j   = jg * 2 + jj;
            const int cbj = jj ? cB1 : cB0;

            if (t < NN) row_s1[t] = 0.f;
            if (t < LL) col_s2[t] = 0.f;

            if (j == i && t < NN) {
                float dflt = (tm_s[t] && cbj > 0) ? 0.f : (1.f / 64.f);
                float* Pp = g_P + (size_t)i * LL * NN + t;
#pragma unroll 8
                for (int l = 0; l < LL; l++) Pp[l * NN] = dflt;
            }
            __syncthreads();

            if (t < cA && cbj > 0) {
                const float* ar = att + t * 132 + jj * 64;
                float mx = -INFINITY;
                for (int c2 = 0; c2 < cbj; c2++) mx = fmaxf(mx, ar[c2]);
                float Z = 0.f, num = 0.f;
                for (int c2 = 0; c2 < cbj; c2++) {
                    float av = ar[c2];
                    float e = fexp(av - mx);
                    Z += e;
                    num += e * av;
                }
                float inv = __frcp_rn(Z);
                row_s1[t] = num * inv;
                if (j == i) {
                    int n = mapA_s[t];
                    float* Pp = g_P + (size_t)i * LL * NN + n;
                    for (int c2 = 0; c2 < cbj; c2++)
                        Pp[mapB_s[jj * 64 + c2] * NN] = fexp(ar[c2] - mx) * inv;
                }
            }
            __syncthreads();

            {   // col softmax: ALL lanes execute (full-warp shfl)
                const int cc = t >> 2, seg = t & 3;
                const int rN = (cA > 0) ? cA : 0;
                const float* ac = att + jj * 64 + cc;
                float mx = -INFINITY;
                for (int r = seg; r < rN; r += 4) mx = fmaxf(mx, ac[r * 132]);
                mx = fmaxf(mx, __shfl_xor_sync(~0u, mx, 1));
                mx = fmaxf(mx, __shfl_xor_sync(~0u, mx, 2));
                float Z = 0.f, num = 0.f;
                for (int r = seg; r < rN; r += 4) {
                    float av = ac[r * 132];
                    float e = fexp(av - mx);
                    Z += e;
                    num += e * av;
                }
                Z += __shfl_xor_sync(~0u, Z, 1);  Z += __shfl_xor_sync(~0u, Z, 2);
                num += __shfl_xor_sync(~0u, num, 1); num += __shfl_xor_sync(~0u, num, 2);
                if (seg == 0 && cc < cbj && rN > 0) col_s2[cc] = num * __frcp_rn(Z);
            }
            __syncthreads();

            if (t < 32) {
                float s = row_s1[t * 4] + row_s1[t * 4 + 1] + row_s1[t * 4 + 2] + row_s1[t * 4 + 3]
                        + col_s2[t * 2] + col_s2[t * 2 + 1];
#pragma unroll
                for (int o = 16; o > 0; o >>= 1) s += __shfl_xor_sync(~0u, s, o);
                if (t == 0) g_S[i * BB + j] = s * (1.f / 128.f);
            }
            __syncthreads();
        }
    }
}

// ---------------------------------------------------------------------------
// Kernel B: contrastive loss from S
// ---------------------------------------------------------------------------
__global__ void loss_kernel(float* __restrict__ out)
{
    __shared__ float Ss[BB * BB];
    __shared__ float part[BB];
    const int t = threadIdx.x;  // 64
    for (int k = t; k < BB * BB; k += BB) Ss[k] = g_S[k];
    __syncthreads();
    float mx = -INFINITY;
    for (int c = 0; c < BB; c++) mx = fmaxf(mx, Ss[t * BB + c]);
    float Z = 0.f;
    for (int c = 0; c < BB; c++) Z += expf(Ss[t * BB + c] - mx);
    float lse_r = mx + logf(Z);
    float mc = -INFINITY;
    for (int r = 0; r < BB; r++) mc = fmaxf(mc, Ss[r * BB + t]);
    float Zc = 0.f;
    for (int r = 0; r < BB; r++) Zc += expf(Ss[r * BB + t] - mc);
    float lse_c = mc + logf(Zc);
    float d = Ss[t * BB + t];
    part[t] = (d - lse_r) + (d - lse_c);
    __syncthreads();
    if (t == 0) {
        float s = 0.f;
        for (int k = 0; k < BB; k++) s += part[k];
        out[0] = -s / (float)BB;
    }
}

// ---------------------------------------------------------------------------
// Kernel C: text_emb_i2s[b] = P[b] @ V[b]  (P stored [l][n])
// ---------------------------------------------------------------------------
__global__ __launch_bounds__(256)
void i2s_kernel(const float* __restrict__ img, float* __restrict__ out)
{
    extern __shared__ float cs[];
    float* V_s = cs;
    float* P_s = cs + 64 * 128;
    const int b = blockIdx.y, dc = blockIdx.x, t = threadIdx.x;
    const int dq = t & 31, ng = t >> 5;

    const float* Vg = img + (size_t)b * LL * DD + dc * 128;
#pragma unroll
    for (int q = 0; q < 8; q++) {
        int f = t + q * 256;
        int l = f >> 5, c4 = f & 31;
        *(float4*)&V_s[l * 128 + c4 * 4] = *(const float4*)(Vg + l * DD + c4 * 4);
    }
    const float* Pgp = g_P + (size_t)b * LL * NN;
#pragma unroll
    for (int q = 0; q < 8; q++) {
        int f = t + q * 256;
        *(float4*)&P_s[f * 4] = *(const float4*)(Pgp + f * 4);
    }
    __syncthreads();

    unsigned long long acc[8][4];
#pragma unroll
    for (int nn = 0; nn < 8; nn++)
#pragma unroll
        for (int dd = 0; dd < 4; dd++) acc[nn][dd] = 0ull;

#pragma unroll 4
    for (int l = 0; l < LL; l++) {
        float v0 = V_s[l * 128 + dq];
        float v1 = V_s[l * 128 + dq + 32];
        float v2 = V_s[l * 128 + dq + 64];
        float v3 = V_s[l * 128 + dq + 96];
        unsigned long long bv0 = pack2(v0, v0), bv1 = pack2(v1, v1);
        unsigned long long bv2 = pack2(v2, v2), bv3 = pack2(v3, v3);
#pragma unroll
        for (int nn = 0; nn < 8; nn++) {
            int np = ng * 8 + nn;
            unsigned long long a = *(const unsigned long long*)&P_s[l * 128 + np * 2];
            ffma2(acc[nn][0], a, bv0);
            ffma2(acc[nn][1], a, bv1);
            ffma2(acc[nn][2], a, bv2);
            ffma2(acc[nn][3], a, bv3);
        }
    }
    float* ob = out + 1 + (size_t)b * NN * DD + dc * 128;
#pragma unroll
    for (int nn = 0; nn < 8; nn++) {
        int n0 = (ng * 8 + nn) * 2;
#pragma unroll
        for (int dd = 0; dd < 4; dd++) {
            float2 v = unpack2(acc[nn][dd]);
            ob[(size_t)n0 * DD + dd * 32 + dq]       = v.x;
            ob[(size_t)(n0 + 1) * DD + dd * 32 + dq] = v.y;
        }
    }
}

// ---------------------------------------------------------------------------
extern "C" void kernel_launch(void* const* d_in, const int* in_sizes, int n_in,
                              void* d_out, int out_size)
{
    (void)in_sizes; (void)n_in; (void)out_size;
    const float* text = (const float*)d_in[0];
    const float* img  = (const float*)d_in[1];
    const int* tmask  = (const int*)d_in[2];
    const int* imask  = (const int*)d_in[3];
    float* out = (float*)d_out;

    cudaFuncSetAttribute(ground6, cudaFuncAttributeMaxDynamicSharedMemorySize, 131072);
    cudaFuncSetAttribute(i2s_kernel, cudaFuncAttributeMaxDynamicSharedMemorySize, 65536);

    conv2<<<dim3(BB, 4), 256>>>(text, img, tmask, imask);
    ground6<<<148, 256, 131072>>>(tmask);
    loss_kernel<<<1, 64>>>(out);
    i2s_kernel<<<dim3(6, BB), 256, 65536>>>(img, out);
}

// round 14
// speedup vs baseline: 1.0828x; 1.0828x over previous
#include <cuda_runtime.h>
#include <cuda_bf16.h>
#include <math.h>
#include <stdint.h>

#define BB 64
#define NN 128
#define LL 64
#define DD 768
#define NEGV (-9e9f)
#define NCH 12            // K chunks of 64

// -------- device scratch (no cudaMalloc allowed) ---------------------------
__device__ __nv_bfloat16 g_tAh[BB * NN * DD];
__device__ __nv_bfloat16 g_tAl[BB * NN * DD];
__device__ __nv_bfloat16 g_tBh[BB * LL * DD];
__device__ __nv_bfloat16 g_tBl[BB * LL * DD];
__device__ float g_S[BB * BB];
__device__ float g_P[BB * LL * NN];
__device__ int g_cA[BB];
__device__ int g_cB[BB];
__device__ int g_mapA[BB][NN];
__device__ int g_mapB[BB][LL];

// -------- helpers ----------------------------------------------------------
__device__ __forceinline__ uint32_t smem_u32(const void* p) {
    uint32_t a;
    asm("{ .reg .u64 t; cvta.to.shared.u64 t, %1; cvt.u32.u64 %0, t; }" : "=r"(a) : "l"(p));
    return a;
}
__device__ __forceinline__ void cp16(uint32_t dst, const void* src) {
    unsigned long long g = (unsigned long long)__cvta_generic_to_global(src);
    asm volatile("cp.async.cg.shared.global [%0], [%1], 16;" :: "r"(dst), "l"(g));
}
#define CP_COMMIT() asm volatile("cp.async.commit_group;" ::: "memory")

#define LDSM_X4(r0, r1, r2, r3, a) \
    asm volatile("ldmatrix.sync.aligned.m8n8.x4.shared.b16 {%0,%1,%2,%3}, [%4];" \
                 : "=r"(r0), "=r"(r1), "=r"(r2), "=r"(r3) : "r"(a))
#define LDSM_X2(r0, r1, a) \
    asm volatile("ldmatrix.sync.aligned.m8n8.x2.shared.b16 {%0,%1}, [%2];" \
                 : "=r"(r0), "=r"(r1) : "r"(a))

#define MMA_BF16(d, a, b) \
    asm("mma.sync.aligned.m16n8k16.row.col.f32.bf16.bf16.f32 " \
        "{%0,%1,%2,%3},{%4,%5,%6,%7},{%8,%9},{%0,%1,%2,%3};" \
        : "+f"((d)[0]), "+f"((d)[1]), "+f"((d)[2]), "+f"((d)[3]) \
        : "r"((a)[0]), "r"((a)[1]), "r"((a)[2]), "r"((a)[3]), \
          "r"((b)[0]), "r"((b)[1]))

// FMA-pipe exp (no MUFU): exp(x), x<=0, poly exp2 deg-6
__device__ __forceinline__ float fexp(float x) {
    float t = fmaxf(x * 1.44269504089f, -126.f);
    int   ni = __float2int_rn(t);
    float f  = t - (float)ni;
    float p = 1.54653240e-4f;
    p = fmaf(p, f, 1.33335581e-3f);
    p = fmaf(p, f, 9.61812910e-3f);
    p = fmaf(p, f, 5.55041087e-2f);
    p = fmaf(p, f, 2.40226507e-1f);
    p = fmaf(p, f, 6.93147182e-1f);
    p = fmaf(p, f, 1.0f);
    return __int_as_float(__float_as_int(p) + (ni << 23));
}

// f32x2 helpers (i2s kernel)
__device__ __forceinline__ void ffma2(unsigned long long &c, unsigned long long a,
                                      unsigned long long b) {
    asm("fma.rn.f32x2 %0, %1, %2, %0;" : "+l"(c) : "l"(a), "l"(b));
}
__device__ __forceinline__ unsigned long long pack2(float x, float y) {
    unsigned long long r;
    asm("mov.b64 %0, {%1, %2};" : "=l"(r) : "f"(x), "f"(y));
    return r;
}
__device__ __forceinline__ float2 unpack2(unsigned long long v) {
    float2 f;
    asm("mov.b64 {%0, %1}, %2;" : "=f"(f.x), "=f"(f.y) : "l"(v));
    return f;
}

// ---------------------------------------------------------------------------
// Kernel 0: mask-compacting f32 -> bf16 hi/lo split into pre-swizzled chunks.
// ---------------------------------------------------------------------------
__global__ void conv2(const float* __restrict__ text, const float* __restrict__ img,
                      const int* __restrict__ tmask, const int* __restrict__ imask)
{
    __shared__ int fA[NN], fB[LL];
    __shared__ int pfxA[NN + 1], pfxB[LL + 1];
    const int b  = blockIdx.x;
    const int dp = blockIdx.y;       // 0..3
    const int t  = threadIdx.x;      // 256

    if (t < NN) fA[t] = (tmask[b * NN + t] != 0);
    if (t < LL) fB[t] = (imask[b * LL + t] != 0);
    __syncthreads();
    if (t == 0) {
        int s = 0;
        for (int n = 0; n < NN; n++) { pfxA[n] = s; s += fA[n]; }
        pfxA[NN] = s;
        s = 0;
        for (int l = 0; l < LL; l++) { pfxB[l] = s; s += fB[l]; }
        pfxB[LL] = s;
    }
    __syncthreads();
    const int cA = pfxA[NN], cB = pfxB[LL];
    const int cApad = (cA + 15) & ~15;
    const int cBpad = (cB + 7) & ~7;

    if (dp == 0) {
        if (t == 0) { g_cA[b] = cA; g_cB[b] = cB; }
        if (t < NN && fA[t]) g_mapA[b][pfxA[t]] = t;
        if (t < LL && fB[t]) g_mapB[b][pfxB[t]] = t;
    }

    const int d0 = dp * 192;
    for (int idx = t; idx < NN * 192; idx += 256) {
        int n = idx / 192, d = d0 + idx % 192;
        if (fA[n]) {
            float v = text[(size_t)b * NN * DD + n * DD + d];
            __nv_bfloat16 hi = __float2bfloat16(v);
            __nv_bfloat16 lo = __float2bfloat16(v - __bfloat162float(hi));
            int r = pfxA[n];
            int c = d >> 6, kin = d & 63;
            int off = ((b * NCH + c) * NN + r) * 64 + (kin ^ ((r & 7) << 3));
            g_tAh[off] = hi; g_tAl[off] = lo;
        }
    }
    for (int idx = t; idx < (cApad - cA) * 192; idx += 256) {
        int r = cA + idx / 192, d = d0 + idx % 192;
        int c = d >> 6, kin = d & 63;
        int off = ((b * NCH + c) * NN + r) * 64 + (kin ^ ((r & 7) << 3));
        g_tAh[off] = __float2bfloat16(0.f); g_tAl[off] = __float2bfloat16(0.f);
    }
    for (int idx = t; idx < LL * 192; idx += 256) {
        int l = idx / 192, d = d0 + idx % 192;
        if (fB[l]) {
            float v = img[(size_t)b * LL * DD + l * DD + d];
            __nv_bfloat16 hi = __float2bfloat16(v);
            __nv_bfloat16 lo = __float2bfloat16(v - __bfloat162float(hi));
            int r = pfxB[l];
            int c = d >> 6, kin = d & 63;
            int off = ((b * NCH + c) * LL + r) * 64 + (kin ^ ((r & 7) << 3));
            g_tBh[off] = hi; g_tBl[off] = lo;
        }
    }
    for (int idx = t; idx < (cBpad - cB) * 192; idx += 256) {
        int r = cB + idx / 192, d = d0 + idx % 192;
        int c = d >> 6, kin = d & 63;
        int off = ((b * NCH + c) * LL + r) * 64 + (kin ^ ((r & 7) << 3));
        g_tBh[off] = __float2bfloat16(0.f); g_tBl[off] = __float2bfloat16(0.f);
    }
}

// ---------------------------------------------------------------------------
// Stage one K-chunk (64 k) of COMPACTED data, bounds-guarded.
// ---------------------------------------------------------------------------
__device__ __forceinline__ void issue_chunk(uint32_t B0, int i, int jg, int c, int t,
                                            int limA, int cB0p, int cB1p)
{
    const __nv_bfloat16* Ah = g_tAh + (size_t)(i * NCH + c) * (NN * 64);
    const __nv_bfloat16* Al = g_tAl + (size_t)(i * NCH + c) * (NN * 64);
#pragma unroll
    for (int q = 0; q < 4; q++) {
        int idx = t + q * 256;
        if (idx < limA) {
            cp16(B0 + idx * 16, Ah + idx * 8);
            cp16(B0 + 16384 + idx * 16, Al + idx * 8);
        }
    }
#pragma unroll
    for (int q = 0; q < 4; q++) {
        int idx = t + q * 256;
        int row = idx >> 3;
        int jj = row >> 6;
        int srow = row & 63;
        bool ok = jj ? (srow < cB1p) : (srow < cB0p);
        if (ok) {
            size_t so = (size_t)((jg * 2 + jj) * NCH + c) * (LL * 64) + (size_t)(srow * 8 + (idx & 7)) * 8;
            cp16(B0 + 32768 + idx * 16, g_tBh + so);
            cp16(B0 + 49152 + idx * 16, g_tBl + so);
        }
    }
}

// ---------------------------------------------------------------------------
// Kernel A: compacted bf16 3x GEMM + fused masked-softmax epilogue.
// Grid (32 j-groups of 2, 64 i). SMSP-complementary warp tile assignment:
// partners (w, w+4) get opposite mh and offset ng so per-SMSP MMA load is
// balanced. Epilogue row softmax split across thread pairs.
// ---------------------------------------------------------------------------
__global__ __launch_bounds__(256, 1)
void ground7(const int* __restrict__ tmask)
{
    extern __shared__ __align__(16) char dsm[];   // 131072: 2x64KB stage / att
    __shared__ int   tm_s[NN];
    __shared__ int   mapA_s[NN];
    __shared__ int   mapB_s[NN];
    __shared__ float row_s1[NN];
    __shared__ float col_s2[LL];

    const int i  = blockIdx.y;
    const int jg = blockIdx.x;
    const int t  = threadIdx.x;
    const int wid = t >> 5, lane = t & 31;
    const uint32_t sb = smem_u32(dsm);

    const int cA  = g_cA[i];
    const int cApad = (cA + 15) & ~15;
    const int cB0 = g_cB[jg * 2];
    const int cB1 = g_cB[jg * 2 + 1];
    const int cB0p = (cB0 + 7) & ~7;
    const int cB1p = (cB1 + 7) & ~7;

    if (t < NN) {
        tm_s[t]   = tmask[i * NN + t];
        mapA_s[t] = g_mapA[i][t];
        mapB_s[t] = g_mapB[jg * 2 + (t >> 6)][t & 63];
    }

    // ---- SMSP-complementary warp tile assignment --------------------------
    // SMSP = wid & 3; partners (w, w+4). wid<4: (mh=0, ng=wid);
    // wid>=4: (mh=1, ng=(wid+2)&3). Partners differ in mh AND ng offset 2.
    const int mh = wid >> 2;
    const int ng = (wid < 4) ? wid : ((wid + 2) & 3);
    const int TM = cApad >> 4;
    int mrow[4]; int tmA = 0;
#pragma unroll
    for (int mf = 0; mf < 4; mf++) {
        int r = mh + 2 * mf;
        if (r < TM) mrow[tmA++] = r << 4;
    }
    const int T0 = cB0p >> 3, T1 = cB1p >> 3, TT = T0 + T1;
    int ncol[4]; int ntq = 0;
#pragma unroll
    for (int q = 0; q < 4; q++) {
        int p = ng + 4 * q;
        if (p < TT) ncol[ntq++] = (p < T0) ? (p << 3) : (64 + ((p - T0) << 3));
    }

    // lane constants
    const int lr = lane & 15, half = lane >> 4;
    const int xorA = (lr & 7) << 4;
    const int blB = lane & 7;
    const int kBo = ((lane >> 3) & 1) << 4;
    const int xorB2 = blB << 4;

    float acc[4][4][4];
#pragma unroll
    for (int a = 0; a < 4; a++)
#pragma unroll
        for (int b = 0; b < 4; b++)
#pragma unroll
            for (int r = 0; r < 4; r++) acc[a][b][r] = 0.f;

    const int limA = cApad * 8;

    issue_chunk(sb, i, jg, 0, t, limA, cB0p, cB1p);
    CP_COMMIT();

    for (int c = 0; c < NCH; c++) {
        const uint32_t SB = sb + (c & 1) * 65536;
        if (c + 1 < NCH) {
            issue_chunk(sb + ((c + 1) & 1) * 65536, i, jg, c + 1, t, limA, cB0p, cB1p);
            CP_COMMIT();
            asm volatile("cp.async.wait_group 1;" ::: "memory");
        } else {
            asm volatile("cp.async.wait_group 0;" ::: "memory");
        }
        __syncthreads();

        const uint32_t Ah = SB, Al = SB + 16384, Bh = SB + 32768, Bl = SB + 49152;
#pragma unroll
        for (int s = 0; s < 4; s++) {
            const int kb = s * 32;
            const int kaA = (kb | (half << 4)) ^ xorA;
            const int kaB = (kb | kBo) ^ xorB2;

            uint32_t ah[4][4], al[4][4], bh[4][2], bl2[4][2];
#pragma unroll
            for (int v = 0; v < 4; v++) if (v < tmA) {
                int row = mrow[v] + lr;
                LDSM_X4(ah[v][0], ah[v][1], ah[v][2], ah[v][3], Ah + row * 128 + kaA);
                LDSM_X4(al[v][0], al[v][1], al[v][2], al[v][3], Al + row * 128 + kaA);
            }
#pragma unroll
            for (int q = 0; q < 4; q++) if (q < ntq) {
                uint32_t off = (uint32_t)(ncol[q] + blB) * 128 + kaB;
                LDSM_X2(bh[q][0],  bh[q][1],  Bh + off);
                LDSM_X2(bl2[q][0], bl2[q][1], Bl + off);
            }
#pragma unroll
            for (int v = 0; v < 4; v++) if (v < tmA)
#pragma unroll
                for (int q = 0; q < 4; q++) if (q < ntq)
                    MMA_BF16(acc[v][q], ah[v], bh[q]);
#pragma unroll
            for (int v = 0; v < 4; v++) if (v < tmA)
#pragma unroll
                for (int q = 0; q < 4; q++) if (q < ntq)
                    MMA_BF16(acc[v][q], ah[v], bl2[q]);
#pragma unroll
            for (int v = 0; v < 4; v++) if (v < tmA)
#pragma unroll
                for (int q = 0; q < 4; q++) if (q < ntq)
                    MMA_BF16(acc[v][q], al[v], bh[q]);
        }
        __syncthreads();
    }

    // ---- att tile -> SMEM (compacted coords), pitch 132 -------------------
    float* att = (float*)dsm;
    const int gr = lane >> 2, cp2 = (lane & 3) * 2;
#pragma unroll
    for (int v = 0; v < 4; v++) if (v < tmA)
#pragma unroll
        for (int q = 0; q < 4; q++) if (q < ntq) {
            int row = mrow[v] + gr;
            int col = ncol[q] + cp2;
            float* d = acc[v][q];
            float2 v0, v1;
            v0.x = (d[0] != 0.f) ? d[0] : NEGV;
            v0.y = (d[1] != 0.f) ? d[1] : NEGV;
            v1.x = (d[2] != 0.f) ? d[2] : NEGV;
            v1.y = (d[3] != 0.f) ? d[3] : NEGV;
            *(float2*)&att[row * 132 + col]       = v0;
            *(float2*)&att[(row + 8) * 132 + col] = v1;
        }
    __syncthreads();

    // ---- epilogue per image batch -----------------------------------------
    for (int jj = 0; jj < 2; jj++) {
        const int j   = jg * 2 + jj;
        const int cbj = jj ? cB1 : cB0;

        if (t < NN) row_s1[t] = 0.f;
        if (t < LL) col_s2[t] = 0.f;

        if (j == i && t < NN) {
            float dflt = (tm_s[t] && cbj > 0) ? 0.f : (1.f / 64.f);
            float* Pp = g_P + (size_t)i * LL * NN + t;
#pragma unroll 8
            for (int l = 0; l < LL; l++) Pp[l * NN] = dflt;
        }
        __syncthreads();

        {   // row softmax: 2 threads per row (pair lanes 2r, 2r+1 share row).
            // ALL lanes execute uniform-trip loops; writes guarded.
            const int rr = t >> 1, sg = t & 1;
            const float* ar = att + rr * 132 + jj * 64;
            float mx = -INFINITY;
            for (int c2 = sg; c2 < cbj; c2 += 2) mx = fmaxf(mx, ar[c2]);
            mx = fmaxf(mx, __shfl_xor_sync(~0u, mx, 1));
            float Z = 0.f, num = 0.f;
            for (int c2 = sg; c2 < cbj; c2 += 2) {
                float av = ar[c2];
                float e = fexp(av - mx);
                Z += e;
                num += e * av;
            }
            Z += __shfl_xor_sync(~0u, Z, 1);
            num += __shfl_xor_sync(~0u, num, 1);
            float inv = __frcp_rn(Z);
            if (sg == 0 && rr < cA && cbj > 0) row_s1[rr] = num * inv;
            if (j == i && rr < cA && cbj > 0) {   // scatter (both pair lanes, disjoint c2)
                int n = mapA_s[rr];
                float* Pp = g_P + (size_t)i * LL * NN + n;
                for (int c2 = sg; c2 < cbj; c2 += 2)
                    Pp[mapB_s[jj * 64 + c2] * NN] = fexp(ar[c2] - mx) * inv;
            }
        }
        __syncthreads();

        {   // col softmax: ALL lanes execute (full-warp shfl)
            const int cc = t >> 2, seg = t & 3;
            const int rN = (cA > 0) ? cA : 0;
            const float* ac = att + jj * 64 + cc;
            float mx = -INFINITY;
            for (int r = seg; r < rN; r += 4) mx = fmaxf(mx, ac[r * 132]);
            mx = fmaxf(mx, __shfl_xor_sync(~0u, mx, 1));
            mx = fmaxf(mx, __shfl_xor_sync(~0u, mx, 2));
            float Z = 0.f, num = 0.f;
            for (int r = seg; r < rN; r += 4) {
                float av = ac[r * 132];
                float e = fexp(av - mx);
                Z += e;
                num += e * av;
            }
            Z += __shfl_xor_sync(~0u, Z, 1);  Z += __shfl_xor_sync(~0u, Z, 2);
            num += __shfl_xor_sync(~0u, num, 1); num += __shfl_xor_sync(~0u, num, 2);
            if (seg == 0 && cc < cbj && rN > 0) col_s2[cc] = num * __frcp_rn(Z);
        }
        __syncthreads();

        if (t < 32) {
            float s = row_s1[t * 4] + row_s1[t * 4 + 1] + row_s1[t * 4 + 2] + row_s1[t * 4 + 3]
                    + col_s2[t * 2] + col_s2[t * 2 + 1];
#pragma unroll
            for (int o = 16; o > 0; o >>= 1) s += __shfl_xor_sync(~0u, s, o);
            if (t == 0) g_S[i * BB + j] = s * (1.f / 128.f);
        }
        __syncthreads();
    }
}

// ---------------------------------------------------------------------------
// Kernel B: contrastive loss from S
// ---------------------------------------------------------------------------
__global__ void loss_kernel(float* __restrict__ out)
{
    __shared__ float Ss[BB * BB];
    __shared__ float part[BB];
    const int t = threadIdx.x;  // 64
    for (int k = t; k < BB * BB; k += BB) Ss[k] = g_S[k];
    __syncthreads();
    float mx = -INFINITY;
    for (int c = 0; c < BB; c++) mx = fmaxf(mx, Ss[t * BB + c]);
    float Z = 0.f;
    for (int c = 0; c < BB; c++) Z += expf(Ss[t * BB + c] - mx);
    float lse_r = mx + logf(Z);
    float mc = -INFINITY;
    for (int r = 0; r < BB; r++) mc = fmaxf(mc, Ss[r * BB + t]);
    float Zc = 0.f;
    for (int r = 0; r < BB; r++) Zc += expf(Ss[r * BB + t] - mc);
    float lse_c = mc + logf(Zc);
    float d = Ss[t * BB + t];
    part[t] = (d - lse_r) + (d - lse_c);
    __syncthreads();
    if (t == 0) {
        float s = 0.f;
        for (int k = 0; k < BB; k++) s += part[k];
        out[0] = -s / (float)BB;
    }
}

// ---------------------------------------------------------------------------
// Kernel C: text_emb_i2s[b] = P[b] @ V[b]  (P stored [l][n])
// ---------------------------------------------------------------------------
__global__ __launch_bounds__(256)
void i2s_kernel(const float* __restrict__ img, float* __restrict__ out)
{
    extern __shared__ float cs[];
    float* V_s = cs;
    float* P_s = cs + 64 * 128;
    const int b = blockIdx.y, dc = blockIdx.x, t = threadIdx.x;
    const int dq = t & 31, ng = t >> 5;

    const float* Vg = img + (size_t)b * LL * DD + dc * 128;
#pragma unroll
    for (int q = 0; q < 8; q++) {
        int f = t + q * 256;
        int l = f >> 5, c4 = f & 31;
        *(float4*)&V_s[l * 128 + c4 * 4] = *(const float4*)(Vg + l * DD + c4 * 4);
    }
    const float* Pgp = g_P + (size_t)b * LL * NN;
#pragma unroll
    for (int q = 0; q < 8; q++) {
        int f = t + q * 256;
        *(float4*)&P_s[f * 4] = *(const float4*)(Pgp + f * 4);
    }
    __syncthreads();

    unsigned long long acc[8][4];
#pragma unroll
    for (int nn = 0; nn < 8; nn++)
#pragma unroll
        for (int dd = 0; dd < 4; dd++) acc[nn][dd] = 0ull;

#pragma unroll 4
    for (int l = 0; l < LL; l++) {
        float v0 = V_s[l * 128 + dq];
        float v1 = V_s[l * 128 + dq + 32];
        float v2 = V_s[l * 128 + dq + 64];
        float v3 = V_s[l * 128 + dq + 96];
        unsigned long long bv0 = pack2(v0, v0), bv1 = pack2(v1, v1);
        unsigned long long bv2 = pack2(v2, v2), bv3 = pack2(v3, v3);
#pragma unroll
        for (int nn = 0; nn < 8; nn++) {
            int np = ng * 8 + nn;
            unsigned long long a = *(const unsigned long long*)&P_s[l * 128 + np * 2];
            ffma2(acc[nn][0], a, bv0);
            ffma2(acc[nn][1], a, bv1);
            ffma2(acc[nn][2], a, bv2);
            ffma2(acc[nn][3], a, bv3);
        }
    }
    float* ob = out + 1 + (size_t)b * NN * DD + dc * 128;
#pragma unroll
    for (int nn = 0; nn < 8; nn++) {
        int n0 = (ng * 8 + nn) * 2;
#pragma unroll
        for (int dd = 0; dd < 4; dd++) {
            float2 v = unpack2(acc[nn][dd]);
            ob[(size_t)n0 * DD + dd * 32 + dq]       = v.x;
            ob[(size_t)(n0 + 1) * DD + dd * 32 + dq] = v.y;
        }
    }
}

// ---------------------------------------------------------------------------
extern "C" void kernel_launch(void* const* d_in, const int* in_sizes, int n_in,
                              void* d_out, int out_size)
{
    (void)in_sizes; (void)n_in; (void)out_size;
    const float* text = (const float*)d_in[0];
    const float* img  = (const float*)d_in[1];
    const int* tmask  = (const int*)d_in[2];
    const int* imask  = (const int*)d_in[3];
    float* out = (float*)d_out;

    cudaFuncSetAttribute(ground7, cudaFuncAttributeMaxDynamicSharedMemorySize, 131072);
    cudaFuncSetAttribute(i2s_kernel, cudaFuncAttributeMaxDynamicSharedMemorySize, 65536);

    conv2<<<dim3(BB, 4), 256>>>(text, img, tmask, imask);
    ground7<<<dim3(32, BB), 256, 131072>>>(tmask);
    loss_kernel<<<1, 64>>>(out);
    i2s_kernel<<<dim3(6, BB), 256, 65536>>>(img, out);
}

// round 15
// speedup vs baseline: 1.0913x; 1.0079x over previous
#include <cuda_runtime.h>
#include <cuda_bf16.h>
#include <math.h>
#include <stdint.h>

#define BB 64
#define NN 128
#define LL 64
#define DD 768
#define NEGV (-9e9f)
#define NCH 12            // K chunks of 64
#define STGB 65536        // bytes per pipeline stage
#define NSTG 3

// -------- device scratch (no cudaMalloc allowed) ---------------------------
__device__ __nv_bfloat16 g_tAh[BB * NN * DD];
__device__ __nv_bfloat16 g_tAl[BB * NN * DD];
__device__ __nv_bfloat16 g_tBh[BB * LL * DD];
__device__ __nv_bfloat16 g_tBl[BB * LL * DD];
__device__ float g_S[BB * BB];
__device__ float g_P[BB * LL * NN];
__device__ int g_cA[BB];
__device__ int g_cB[BB];
__device__ int g_mapA[BB][NN];
__device__ int g_mapB[BB][LL];

// -------- helpers ----------------------------------------------------------
__device__ __forceinline__ uint32_t smem_u32(const void* p) {
    uint32_t a;
    asm("{ .reg .u64 t; cvta.to.shared.u64 t, %1; cvt.u32.u64 %0, t; }" : "=r"(a) : "l"(p));
    return a;
}
__device__ __forceinline__ void cp16(uint32_t dst, const void* src) {
    unsigned long long g = (unsigned long long)__cvta_generic_to_global(src);
    asm volatile("cp.async.cg.shared.global [%0], [%1], 16;" :: "r"(dst), "l"(g));
}
#define CP_COMMIT() asm volatile("cp.async.commit_group;" ::: "memory")

#define LDSM_X4(r0, r1, r2, r3, a) \
    asm volatile("ldmatrix.sync.aligned.m8n8.x4.shared.b16 {%0,%1,%2,%3}, [%4];" \
                 : "=r"(r0), "=r"(r1), "=r"(r2), "=r"(r3) : "r"(a))
#define LDSM_X2(r0, r1, a) \
    asm volatile("ldmatrix.sync.aligned.m8n8.x2.shared.b16 {%0,%1}, [%2];" \
                 : "=r"(r0), "=r"(r1) : "r"(a))

#define MMA_BF16(d, a, b) \
    asm("mma.sync.aligned.m16n8k16.row.col.f32.bf16.bf16.f32 " \
        "{%0,%1,%2,%3},{%4,%5,%6,%7},{%8,%9},{%0,%1,%2,%3};" \
        : "+f"((d)[0]), "+f"((d)[1]), "+f"((d)[2]), "+f"((d)[3]) \
        : "r"((a)[0]), "r"((a)[1]), "r"((a)[2]), "r"((a)[3]), \
          "r"((b)[0]), "r"((b)[1]))

// FMA-pipe exp (no MUFU): exp(x), x<=0, poly exp2 deg-6
__device__ __forceinline__ float fexp(float x) {
    float t = fmaxf(x * 1.44269504089f, -126.f);
    int   ni = __float2int_rn(t);
    float f  = t - (float)ni;
    float p = 1.54653240e-4f;
    p = fmaf(p, f, 1.33335581e-3f);
    p = fmaf(p, f, 9.61812910e-3f);
    p = fmaf(p, f, 5.55041087e-2f);
    p = fmaf(p, f, 2.40226507e-1f);
    p = fmaf(p, f, 6.93147182e-1f);
    p = fmaf(p, f, 1.0f);
    return __int_as_float(__float_as_int(p) + (ni << 23));
}

// f32x2 helpers (i2s kernel)
__device__ __forceinline__ void ffma2(unsigned long long &c, unsigned long long a,
                                      unsigned long long b) {
    asm("fma.rn.f32x2 %0, %1, %2, %0;" : "+l"(c) : "l"(a), "l"(b));
}
__device__ __forceinline__ unsigned long long pack2(float x, float y) {
    unsigned long long r;
    asm("mov.b64 %0, {%1, %2};" : "=l"(r) : "f"(x), "f"(y));
    return r;
}
__device__ __forceinline__ float2 unpack2(unsigned long long v) {
    float2 f;
    asm("mov.b64 {%0, %1}, %2;" : "=f"(f.x), "=f"(f.y) : "l"(v));
    return f;
}

// ---------------------------------------------------------------------------
// Kernel 0: mask-compacting f32 -> bf16 hi/lo split into pre-swizzled chunks.
// ---------------------------------------------------------------------------
__global__ void conv2(const float* __restrict__ text, const float* __restrict__ img,
                      const int* __restrict__ tmask, const int* __restrict__ imask)
{
    __shared__ int fA[NN], fB[LL];
    __shared__ int pfxA[NN + 1], pfxB[LL + 1];
    const int b  = blockIdx.x;
    const int dp = blockIdx.y;       // 0..3
    const int t  = threadIdx.x;      // 256

    if (t < NN) fA[t] = (tmask[b * NN + t] != 0);
    if (t < LL) fB[t] = (imask[b * LL + t] != 0);
    __syncthreads();
    if (t == 0) {
        int s = 0;
        for (int n = 0; n < NN; n++) { pfxA[n] = s; s += fA[n]; }
        pfxA[NN] = s;
        s = 0;
        for (int l = 0; l < LL; l++) { pfxB[l] = s; s += fB[l]; }
        pfxB[LL] = s;
    }
    __syncthreads();
    const int cA = pfxA[NN], cB = pfxB[LL];
    const int cApad = (cA + 15) & ~15;
    const int cBpad = (cB + 7) & ~7;

    if (dp == 0) {
        if (t == 0) { g_cA[b] = cA; g_cB[b] = cB; }
        if (t < NN && fA[t]) g_mapA[b][pfxA[t]] = t;
        if (t < LL && fB[t]) g_mapB[b][pfxB[t]] = t;
    }

    const int d0 = dp * 192;
    for (int idx = t; idx < NN * 192; idx += 256) {
        int n = idx / 192, d = d0 + idx % 192;
        if (fA[n]) {
            float v = text[(size_t)b * NN * DD + n * DD + d];
            __nv_bfloat16 hi = __float2bfloat16(v);
            __nv_bfloat16 lo = __float2bfloat16(v - __bfloat162float(hi));
            int r = pfxA[n];
            int c = d >> 6, kin = d & 63;
            int off = ((b * NCH + c) * NN + r) * 64 + (kin ^ ((r & 7) << 3));
            g_tAh[off] = hi; g_tAl[off] = lo;
        }
    }
    for (int idx = t; idx < (cApad - cA) * 192; idx += 256) {
        int r = cA + idx / 192, d = d0 + idx % 192;
        int c = d >> 6, kin = d & 63;
        int off = ((b * NCH + c) * NN + r) * 64 + (kin ^ ((r & 7) << 3));
        g_tAh[off] = __float2bfloat16(0.f); g_tAl[off] = __float2bfloat16(0.f);
    }
    for (int idx = t; idx < LL * 192; idx += 256) {
        int l = idx / 192, d = d0 + idx % 192;
        if (fB[l]) {
            float v = img[(size_t)b * LL * DD + l * DD + d];
            __nv_bfloat16 hi = __float2bfloat16(v);
            __nv_bfloat16 lo = __float2bfloat16(v - __bfloat162float(hi));
            int r = pfxB[l];
            int c = d >> 6, kin = d & 63;
            int off = ((b * NCH + c) * LL + r) * 64 + (kin ^ ((r & 7) << 3));
            g_tBh[off] = hi; g_tBl[off] = lo;
        }
    }
    for (int idx = t; idx < (cBpad - cB) * 192; idx += 256) {
        int r = cB + idx / 192, d = d0 + idx % 192;
        int c = d >> 6, kin = d & 63;
        int off = ((b * NCH + c) * LL + r) * 64 + (kin ^ ((r & 7) << 3));
        g_tBh[off] = __float2bfloat16(0.f); g_tBl[off] = __float2bfloat16(0.f);
    }
}

// ---------------------------------------------------------------------------
// Stage one K-chunk (64 k) of COMPACTED data, bounds-guarded.
// ---------------------------------------------------------------------------
__device__ __forceinline__ void issue_chunk(uint32_t B0, int i, int jg, int c, int t,
                                            int limA, int cB0p, int cB1p)
{
    const __nv_bfloat16* Ah = g_tAh + (size_t)(i * NCH + c) * (NN * 64);
    const __nv_bfloat16* Al = g_tAl + (size_t)(i * NCH + c) * (NN * 64);
#pragma unroll
    for (int q = 0; q < 4; q++) {
        int idx = t + q * 256;
        if (idx < limA) {
            cp16(B0 + idx * 16, Ah + idx * 8);
            cp16(B0 + 16384 + idx * 16, Al + idx * 8);
        }
    }
#pragma unroll
    for (int q = 0; q < 4; q++) {
        int idx = t + q * 256;
        int row = idx >> 3;
        int jj = row >> 6;
        int srow = row & 63;
        bool ok = jj ? (srow < cB1p) : (srow < cB0p);
        if (ok) {
            size_t so = (size_t)((jg * 2 + jj) * NCH + c) * (LL * 64) + (size_t)(srow * 8 + (idx & 7)) * 8;
            cp16(B0 + 32768 + idx * 16, g_tBh + so);
            cp16(B0 + 49152 + idx * 16, g_tBl + so);
        }
    }
}

// ---------------------------------------------------------------------------
// Kernel A: compacted bf16 3x GEMM + fused softmax epilogue.
// 3-stage cp.async pipeline, ONE barrier per chunk, streamlined epilogue.
// ---------------------------------------------------------------------------
__global__ __launch_bounds__(256, 1)
void ground8(const int* __restrict__ tmask)
{
    extern __shared__ __align__(16) char dsm[];   // 196608: 3 x 64KB stages / att
    __shared__ int   tm_s[NN];
    __shared__ int   mapA_s[NN];
    __shared__ int   mapB_s[NN];
    __shared__ float row_s1[NN];
    __shared__ float col_s2[LL];

    const int i  = blockIdx.y;
    const int jg = blockIdx.x;
    const int t  = threadIdx.x;
    const int wid = t >> 5, lane = t & 31;
    const uint32_t sb = smem_u32(dsm);

    const int cA  = g_cA[i];
    const int cApad = (cA + 15) & ~15;
    const int cB0 = g_cB[jg * 2];
    const int cB1 = g_cB[jg * 2 + 1];
    const int cB0p = (cB0 + 7) & ~7;
    const int cB1p = (cB1 + 7) & ~7;
    const int diag_jj = (jg == (i >> 1)) ? (i & 1) : -1;

    if (t < NN) {
        tm_s[t]   = tmask[i * NN + t];
        mapA_s[t] = g_mapA[i][t];
        mapB_s[t] = g_mapB[jg * 2 + (t >> 6)][t & 63];
    }

    // g_P default fill (diag CTA only): masked row or empty cols -> 1/64, else 0.
    // Thread t reads tm_s[t] which it wrote itself — no barrier needed.
    if (diag_jj >= 0 && t < NN) {
        const int cbd = diag_jj ? cB1 : cB0;
        int tmv = tmask[i * NN + t];
        float dflt = (tmv && cbd > 0) ? 0.f : (1.f / 64.f);
        float* Pp = g_P + (size_t)i * LL * NN + t;
#pragma unroll 8
        for (int l = 0; l < LL; l++) Pp[l * NN] = dflt;
    }

    // ---- SMSP-complementary warp tile assignment --------------------------
    const int mh = wid >> 2;
    const int ng = (wid < 4) ? wid : ((wid + 2) & 3);
    const int TM = cApad >> 4;
    int mrow[4]; int tmA = 0;
#pragma unroll
    for (int mf = 0; mf < 4; mf++) {
        int r = mh + 2 * mf;
        if (r < TM) mrow[tmA++] = r << 4;
    }
    const int T0 = cB0p >> 3, T1 = cB1p >> 3, TT = T0 + T1;
    int ncol[4]; int ntq = 0;
#pragma unroll
    for (int q = 0; q < 4; q++) {
        int p = ng + 4 * q;
        if (p < TT) ncol[ntq++] = (p < T0) ? (p << 3) : (64 + ((p - T0) << 3));
    }

    // lane constants
    const int lr = lane & 15, half = lane >> 4;
    const int xorA = (lr & 7) << 4;
    const int blB = lane & 7;
    const int kBo = ((lane >> 3) & 1) << 4;
    const int xorB2 = blB << 4;

    float acc[4][4][4];
#pragma unroll
    for (int a = 0; a < 4; a++)
#pragma unroll
        for (int b = 0; b < 4; b++)
#pragma unroll
            for (int r = 0; r < 4; r++) acc[a][b][r] = 0.f;

    const int limA = cApad * 8;

    // prime 2 stages
    issue_chunk(sb + 0 * STGB, i, jg, 0, t, limA, cB0p, cB1p);
    CP_COMMIT();
    issue_chunk(sb + 1 * STGB, i, jg, 1, t, limA, cB0p, cB1p);
    CP_COMMIT();

    int stg = 0;
    for (int c = 0; c < NCH; c++) {
        if (c + 1 < NCH) {
            asm volatile("cp.async.wait_group 1;" ::: "memory");
        } else {
            asm volatile("cp.async.wait_group 0;" ::: "memory");
        }
        __syncthreads();   // all warps: chunk c visible AND done reading chunk c-1

        if (c + 2 < NCH) {  // refill the stage that held chunk c-1
            int nst = stg + 2; if (nst >= NSTG) nst -= NSTG;
            issue_chunk(sb + nst * STGB, i, jg, c + 2, t, limA, cB0p, cB1p);
            CP_COMMIT();
        }

        const uint32_t SB = sb + stg * STGB;
        const uint32_t Ah = SB, Al = SB + 16384, Bh = SB + 32768, Bl = SB + 49152;
#pragma unroll
        for (int s = 0; s < 4; s++) {
            const int kb = s * 32;
            const int kaA = (kb | (half << 4)) ^ xorA;
            const int kaB = (kb | kBo) ^ xorB2;

            uint32_t ah[4][4], al[4][4], bh[4][2], bl2[4][2];
#pragma unroll
            for (int v = 0; v < 4; v++) if (v < tmA) {
                int row = mrow[v] + lr;
                LDSM_X4(ah[v][0], ah[v][1], ah[v][2], ah[v][3], Ah + row * 128 + kaA);
                LDSM_X4(al[v][0], al[v][1], al[v][2], al[v][3], Al + row * 128 + kaA);
            }
#pragma unroll
            for (int q = 0; q < 4; q++) if (q < ntq) {
                uint32_t off = (uint32_t)(ncol[q] + blB) * 128 + kaB;
                LDSM_X2(bh[q][0],  bh[q][1],  Bh + off);
                LDSM_X2(bl2[q][0], bl2[q][1], Bl + off);
            }
#pragma unroll
            for (int v = 0; v < 4; v++) if (v < tmA)
#pragma unroll
                for (int q = 0; q < 4; q++) if (q < ntq)
                    MMA_BF16(acc[v][q], ah[v], bh[q]);
#pragma unroll
            for (int v = 0; v < 4; v++) if (v < tmA)
#pragma unroll
                for (int q = 0; q < 4; q++) if (q < ntq)
                    MMA_BF16(acc[v][q], ah[v], bl2[q]);
#pragma unroll
            for (int v = 0; v < 4; v++) if (v < tmA)
#pragma unroll
                for (int q = 0; q < 4; q++) if (q < ntq)
                    MMA_BF16(acc[v][q], al[v], bh[q]);
        }
        if (++stg >= NSTG) stg = 0;
        // no end-of-chunk barrier (3-stage safety argument in header comment)
    }
    __syncthreads();   // all warps finished mainloop before att overwrites stages

    // ---- att tile -> SMEM (compacted coords), pitch 132 -------------------
    float* att = (float*)dsm;
    const int gr = lane >> 2, cp2 = (lane & 3) * 2;
#pragma unroll
    for (int v = 0; v < 4; v++) if (v < tmA)
#pragma unroll
        for (int q = 0; q < 4; q++) if (q < ntq) {
            int row = mrow[v] + gr;
            int col = ncol[q] + cp2;
            float* d = acc[v][q];
            float2 v0, v1;
            v0.x = (d[0] != 0.f) ? d[0] : NEGV;
            v0.y = (d[1] != 0.f) ? d[1] : NEGV;
            v1.x = (d[2] != 0.f) ? d[2] : NEGV;
            v1.y = (d[3] != 0.f) ? d[3] : NEGV;
            *(float2*)&att[row * 132 + col]       = v0;
            *(float2*)&att[(row + 8) * 132 + col] = v1;
        }
    __syncthreads();

    // ---- epilogue per image batch -----------------------------------------
    for (int jj = 0; jj < 2; jj++) {
        const int j   = jg * 2 + jj;
        const int cbj = jj ? cB1 : cB0;

        {   // row softmax: 2 threads per row; unconditional store (val or 0)
            const int rr = t >> 1, sg = t & 1;
            const float* ar = att + rr * 132 + jj * 64;
            float mx = -INFINITY;
            for (int c2 = sg; c2 < cbj; c2 += 2) mx = fmaxf(mx, ar[c2]);
            mx = fmaxf(mx, __shfl_xor_sync(~0u, mx, 1));
            float Z = 0.f, num = 0.f;
            for (int c2 = sg; c2 < cbj; c2 += 2) {
                float av = ar[c2];
                float e = fexp(av - mx);
                Z += e;
                num += e * av;
            }
            Z += __shfl_xor_sync(~0u, Z, 1);
            num += __shfl_xor_sync(~0u, num, 1);
            float inv = __frcp_rn(Z);
            if (sg == 0) row_s1[rr] = (rr < cA && cbj > 0) ? num * inv : 0.f;
            if (jj == diag_jj && rr < cA && cbj > 0) {   // scatter (disjoint c2 per lane)
                int n = mapA_s[rr];
                float* Pp = g_P + (size_t)i * LL * NN + n;
                for (int c2 = sg; c2 < cbj; c2 += 2)
                    Pp[mapB_s[jj * 64 + c2] * NN] = fexp(ar[c2] - mx) * inv;
            }
        }
        {   // col softmax (read-only on att, runs back-to-back with row pass)
            const int cc = t >> 2, seg = t & 3;
            const int rN = cA;
            const float* ac = att + jj * 64 + cc;
            float mx = -INFINITY;
            for (int r = seg; r < rN; r += 4) mx = fmaxf(mx, ac[r * 132]);
            mx = fmaxf(mx, __shfl_xor_sync(~0u, mx, 1));
            mx = fmaxf(mx, __shfl_xor_sync(~0u, mx, 2));
            float Z = 0.f, num = 0.f;
            for (int r = seg; r < rN; r += 4) {
                float av = ac[r * 132];
                float e = fexp(av - mx);
                Z += e;
                num += e * av;
            }
            Z += __shfl_xor_sync(~0u, Z, 1);  Z += __shfl_xor_sync(~0u, Z, 2);
            num += __shfl_xor_sync(~0u, num, 1); num += __shfl_xor_sync(~0u, num, 2);
            if (seg == 0) col_s2[cc] = (cc < cbj && rN > 0) ? num * __frcp_rn(Z) : 0.f;
        }
        __syncthreads();

        if (t < 32) {
            float s = row_s1[t * 4] + row_s1[t * 4 + 1] + row_s1[t * 4 + 2] + row_s1[t * 4 + 3]
                    + col_s2[t * 2] + col_s2[t * 2 + 1];
#pragma unroll
            for (int o = 16; o > 0; o >>= 1) s += __shfl_xor_sync(~0u, s, o);
            if (t == 0) g_S[i * BB + j] = s * (1.f / 128.f);
        }
        __syncthreads();   // row_s1/col_s2 consumed before next jj overwrites
    }
}

// ---------------------------------------------------------------------------
// Kernel B: contrastive loss from S
// ---------------------------------------------------------------------------
__global__ void loss_kernel(float* __restrict__ out)
{
    __shared__ float Ss[BB * BB];
    __shared__ float part[BB];
    const int t = threadIdx.x;  // 64
    for (int k = t; k < BB * BB; k += BB) Ss[k] = g_S[k];
    __syncthreads();
    float mx = -INFINITY;
    for (int c = 0; c < BB; c++) mx = fmaxf(mx, Ss[t * BB + c]);
    float Z = 0.f;
    for (int c = 0; c < BB; c++) Z += expf(Ss[t * BB + c] - mx);
    float lse_r = mx + logf(Z);
    float mc = -INFINITY;
    for (int r = 0; r < BB; r++) mc = fmaxf(mc, Ss[r * BB + t]);
    float Zc = 0.f;
    for (int r = 0; r < BB; r++) Zc += expf(Ss[r * BB + t] - mc);
    float lse_c = mc + logf(Zc);
    float d = Ss[t * BB + t];
    part[t] = (d - lse_r) + (d - lse_c);
    __syncthreads();
    if (t == 0) {
        float s = 0.f;
        for (int k = 0; k < BB; k++) s += part[k];
        out[0] = -s / (float)BB;
    }
}

// ---------------------------------------------------------------------------
// Kernel C: text_emb_i2s[b] = P[b] @ V[b]  (P stored [l][n])
// ---------------------------------------------------------------------------
__global__ __launch_bounds__(256)
void i2s_kernel(const float* __restrict__ img, float* __restrict__ out)
{
    extern __shared__ float cs[];
    float* V_s = cs;
    float* P_s = cs + 64 * 128;
    const int b = blockIdx.y, dc = blockIdx.x, t = threadIdx.x;
    const int dq = t & 31, ng = t >> 5;

    const float* Vg = img + (size_t)b * LL * DD + dc * 128;
#pragma unroll
    for (int q = 0; q < 8; q++) {
        int f = t + q * 256;
        int l = f >> 5, c4 = f & 31;
        *(float4*)&V_s[l * 128 + c4 * 4] = *(const float4*)(Vg + l * DD + c4 * 4);
    }
    const float* Pgp = g_P + (size_t)b * LL * NN;
#pragma unroll
    for (int q = 0; q < 8; q++) {
        int f = t + q * 256;
        *(float4*)&P_s[f * 4] = *(const float4*)(Pgp + f * 4);
    }
    __syncthreads();

    unsigned long long acc[8][4];
#pragma unroll
    for (int nn = 0; nn < 8; nn++)
#pragma unroll
        for (int dd = 0; dd < 4; dd++) acc[nn][dd] = 0ull;

#pragma unroll 4
    for (int l = 0; l < LL; l++) {
        float v0 = V_s[l * 128 + dq];
        float v1 = V_s[l * 128 + dq + 32];
        float v2 = V_s[l * 128 + dq + 64];
        float v3 = V_s[l * 128 + dq + 96];
        unsigned long long bv0 = pack2(v0, v0), bv1 = pack2(v1, v1);
        unsigned long long bv2 = pack2(v2, v2), bv3 = pack2(v3, v3);
#pragma unroll
        for (int nn = 0; nn < 8; nn++) {
            int np = ng * 8 + nn;
            unsigned long long a = *(const unsigned long long*)&P_s[l * 128 + np * 2];
            ffma2(acc[nn][0], a, bv0);
            ffma2(acc[nn][1], a, bv1);
            ffma2(acc[nn][2], a, bv2);
            ffma2(acc[nn][3], a, bv3);
        }
    }
    float* ob = out + 1 + (size_t)b * NN * DD + dc * 128;
#pragma unroll
    for (int nn = 0; nn < 8; nn++) {
        int n0 = (ng * 8 + nn) * 2;
#pragma unroll
        for (int dd = 0; dd < 4; dd++) {
            float2 v = unpack2(acc[nn][dd]);
            ob[(size_t)n0 * DD + dd * 32 + dq]       = v.x;
            ob[(size_t)(n0 + 1) * DD + dd * 32 + dq] = v.y;
        }
    }
}

// ---------------------------------------------------------------------------
extern "C" void kernel_launch(void* const* d_in, const int* in_sizes, int n_in,
                              void* d_out, int out_size)
{
    (void)in_sizes; (void)n_in; (void)out_size;
    const float* text = (const float*)d_in[0];
    const float* img  = (const float*)d_in[1];
    const int* tmask  = (const int*)d_in[2];
    const int* imask  = (const int*)d_in[3];
    float* out = (float*)d_out;

    cudaFuncSetAttribute(ground8, cudaFuncAttributeMaxDynamicSharedMemorySize, NSTG * STGB);
    cudaFuncSetAttribute(i2s_kernel, cudaFuncAttributeMaxDynamicSharedMemorySize, 65536);

    conv2<<<dim3(BB, 4), 256>>>(text, img, tmask, imask);
    ground8<<<dim3(32, BB), 256, NSTG * STGB>>>(tmask);
    loss_kernel<<<1, 64>>>(out);
    i2s_kernel<<<dim3(6, BB), 256, 65536>>>(img, out);
}